// round 14
// baseline (speedup 1.0000x reference)
#include <cuda_runtime.h>

#define B  32
#define S  617
#define D  10000
#define L  100
#define C  26
#define W  313        // ceil(D/32) real words
#define WP 320        // padded word count

// ---------------- device globals (pads stay zero forever) ---------------------------------------
__device__ __align__(16) unsigned g_idp[S * WP];   // packed id signs    [s][w]
__device__ __align__(16) unsigned g_lvp[L * WP];   // packed level signs [l][w]
__device__ __align__(16) unsigned g_enc[B * WP];   // packed enc (1 -> +1, 0 -> -1)

// ================= kernel 1: pack sign bits; wide grid, MLP-8 float4 + shfl =====================
#define NROWS (S + L)                        // 717
#define RPR   10                             // regions of 1024 floats per row
#define PREP_WARPS  (NROWS * RPR)            // 7170
#define PREP_BLOCKS ((PREP_WARPS + 7) / 8)   // 897

__global__ __launch_bounds__(256) void prep_kernel(const float* __restrict__ idw,
                                                   const float* __restrict__ lvw) {
    const int lane = threadIdx.x & 31;
    const int gw   = blockIdx.x * 8 + (threadIdx.x >> 5);
    if (gw >= PREP_WARPS) return;

    const int r      = gw / RPR;
    const int region = gw - r * RPR;
    const float* src = (r < S) ? (idw + (size_t)r * D) : (lvw + (size_t)(r - S) * D);
    unsigned*    dst = (r < S) ? (g_idp + r * WP)       : (g_lvp + (r - S) * WP);

    const int qbase = region * 256;

    float4 v[8];
    #pragma unroll
    for (int k = 0; k < 8; k++) {
        int q = qbase + k * 32 + lane;
        if (q < D / 4) v[k] = *reinterpret_cast<const float4*>(src + 4 * q);
        else           v[k] = make_float4(0.f, 0.f, 0.f, 0.f);
    }

    unsigned nib[8];
    #pragma unroll
    for (int k = 0; k < 8; k++) {
        unsigned n = (v[k].x > 0.f ? 1u : 0u) | (v[k].y > 0.f ? 2u : 0u)
                   | (v[k].z > 0.f ? 4u : 0u) | (v[k].w > 0.f ? 8u : 0u);
        n |= __shfl_down_sync(0xffffffffu, n, 1) << 4;
        n |= __shfl_down_sync(0xffffffffu, n, 2) << 8;
        n |= __shfl_down_sync(0xffffffffu, n, 4) << 16;
        nib[k] = n;
    }

    if ((lane & 7) == 0) {
        const int g = lane >> 3;
        #pragma unroll
        for (int k = 0; k < 8; k++) {
            int w = region * 32 + 4 * k + g;
            if (w < W) dst[w] = nib[k];
        }
    }
}

// ---------------- 6-sample bitplane compressor (26 LOP3 per 6 samples) --------------------------
__device__ __forceinline__ void csa6(const unsigned xx[6], unsigned p[7]) {
    unsigned t01 = xx[0] ^ xx[1];
    unsigned l1  = t01 ^ xx[2];
    unsigned h1  = (xx[0] & xx[1]) | (xx[2] & t01);
    unsigned t34 = xx[3] ^ xx[4];
    unsigned l2  = t34 ^ xx[5];
    unsigned h2  = (xx[3] & xx[4]) | (xx[5] & t34);
    unsigned tl = l1 ^ l2;
    unsigned c0 = (l1 & l2) | (p[0] & tl);
    p[0] ^= tl;
    unsigned th  = h1 ^ h2;
    unsigned c1a = (h1 & h2) | (p[1] & th);
    unsigned s1  = p[1] ^ th;
    unsigned c1b = s1 & c0;
    p[1] = s1 ^ c0;
    unsigned tc = c1a ^ c1b;
    unsigned c2 = (c1a & c1b) | (p[2] & tc);
    p[2] ^= tc;
    unsigned t;
    t = p[3] & c2; p[3] ^= c2; c2 = t;
    t = p[4] & c2; p[4] ^= c2; c2 = t;
    t = p[5] & c2; p[5] ^= c2; c2 = t;
    p[6] ^= c2;
}

// ---------------- bit-sliced compare cnt < 309 (309 = 0b0100110101) -----------------------------
__device__ __forceinline__ unsigned cmp309(const unsigned A[10]) {
    unsigned lt = 0u, eq = 0xffffffffu;
    eq &= ~A[9];
    lt |= eq & ~A[8]; eq &= A[8];
    eq &= ~A[7];
    eq &= ~A[6];
    lt |= eq & ~A[5]; eq &= A[5];
    lt |= eq & ~A[4]; eq &= A[4];
    eq &= ~A[3];
    lt |= eq & ~A[2]; eq &= A[2];
    eq &= ~A[1];
    lt |= eq & ~A[0];
    return lt;
}

// ================= kernel 2: bind + count, 2 batches/block, smem-staged level slice =============
// grid (16 batch-pairs, 10 word-groups of 32), 320 threads = 10 sample-group warps.
// Thread = one word (lane) x 2 batches. g_idp word read ONCE per pair (L2 traffic 3x lower),
// level gathers from smem. sidx computed inline from x (g_idx eliminated).
__global__ __launch_bounds__(320) void main_kernel(const float* __restrict__ x) {
    const int b0   = blockIdx.x * 2;        // batches b0, b0+1
    const int wg   = blockIdx.y;            // 0..9, 32-word group
    const int sg   = threadIdx.x >> 5;      // 0..9 sample group
    const int lane = threadIdx.x & 31;
    const int w    = wg * 32 + lane;        // word index
    const int tid  = threadIdx.x;

    __shared__ __align__(16) unsigned lvq[L * 32];        // level slice [l][32 words]  12.8 KB
    __shared__ __align__(16) int      sidx[2][624];       // idx rows for b0, b0+1       5 KB
    __shared__ __align__(16) unsigned pl[2][10 * 7 * 32]; // planes per batch           17.9 KB

    // stage level slice: each warp loads full 128B rows, coalesced
    for (int i = tid; i < L * 32; i += 320)
        lvq[i] = g_lvp[(i >> 5) * WP + wg * 32 + (i & 31)];

    // quantize x rows b0, b0+1 (rintf = half-even, matches jnp.round)
    for (int i = tid; i < S; i += 320) {
        int q0 = (int)rintf(__ldg(&x[(b0 + 0) * S + i]) * (float)(L - 1));
        int q1 = (int)rintf(__ldg(&x[(b0 + 1) * S + i]) * (float)(L - 1));
        sidx[0][i] = min(max(q0, 0), L - 1) << 5;   // pre-scaled row offset
        sidx[1][i] = min(max(q1, 0), L - 1) << 5;
    }
    __syncthreads();

    const int s0 = sg * 62;
    const int sn = (sg == 9) ? 59 : 62;     // 9*62 + 59 = 617

    unsigned pA[7] = {0,0,0,0,0,0,0};       // batch b0
    unsigned pB[7] = {0,0,0,0,0,0,0};       // batch b0+1

    const int full6 = sn / 6;               // 10 or 9
    for (int g = 0; g < full6; g++) {
        unsigned xa[6], xb[6];
        #pragma unroll
        for (int k = 0; k < 6; k++) {
            int s = s0 + g * 6 + k;
            unsigned a = __ldg(&g_idp[s * WP + w]);      // once per 2 batches
            xa[k] = a ^ lvq[sidx[0][s] + lane];
            xb[k] = a ^ lvq[sidx[1][s] + lane];
        }
        csa6(xa, pA);
        csa6(xb, pB);
    }
    for (int s = s0 + full6 * 6; s < s0 + sn; s++) {     // remainder 2 or 5 samples
        unsigned a  = __ldg(&g_idp[s * WP + w]);
        unsigned cA = a ^ lvq[sidx[0][s] + lane];
        unsigned cB = a ^ lvq[sidx[1][s] + lane];
        #pragma unroll
        for (int k = 0; k < 7; k++) {
            unsigned t = pA[k] & cA; pA[k] ^= cA; cA = t;
            t = pB[k] & cB; pB[k] ^= cB; cB = t;
        }
    }

    #pragma unroll
    for (int k = 0; k < 7; k++) {
        pl[0][(sg * 7 + k) * 32 + lane] = pA[k];
        pl[1][(sg * 7 + k) * 32 + lane] = pB[k];
    }
    __syncthreads();

    // warps 0 and 1 merge the 10 sample-groups for batch 0 / 1 respectively
    if (tid < 64) {
        const int bb = tid >> 5;            // 0 or 1
        const int ln = tid & 31;
        unsigned A[10];
        #pragma unroll
        for (int k = 0; k < 10; k++) A[k] = 0u;
        #pragma unroll
        for (int g2 = 0; g2 < 10; g2++) {
            unsigned c = 0u;
            #pragma unroll
            for (int k = 0; k < 7; k++) {
                unsigned q = pl[bb][(g2 * 7 + k) * 32 + ln];
                unsigned s2 = A[k] ^ q ^ c;
                c = (A[k] & q) | (c & (A[k] ^ q));
                A[k] = s2;
            }
            #pragma unroll
            for (int k = 7; k < 10; k++) { unsigned t = A[k] & c; A[k] ^= c; c = t; }
        }
        g_enc[(b0 + bb) * WP + wg * 32 + ln] = cmp309(A);
    }
}

// ================= kernel 3: logits, float4 cw + front-batched loads (R8 geometry) ==============
__global__ __launch_bounds__(320) void logits_kernel(const float* __restrict__ cw,
                                                     float* __restrict__ out) {
    const int c    = blockIdx.x;
    const int b0   = blockIdx.y * 4;
    const int tid  = threadIdx.x;
    const int lane = tid & 31;
    const int wrp  = tid >> 5;
    const int bb   = (tid & 7) * 4;         // bit base within word

    __shared__ __align__(16) uint4 se4[WP];
    __shared__ float red[10][4];
    {
        uint4 v;
        v.x = g_enc[(b0 + 0) * WP + tid];
        v.y = g_enc[(b0 + 1) * WP + tid];
        v.z = g_enc[(b0 + 2) * WP + tid];
        v.w = g_enc[(b0 + 3) * WP + tid];
        se4[tid] = v;
    }
    __syncthreads();

    const float4* cw4 = reinterpret_cast<const float4*>(cw + (size_t)c * D);
    const unsigned MSB = 0x80000000u;

    float4 cv[7];
    uint4  ev[7];
    #pragma unroll
    for (int k = 0; k < 7; k++) cv[k] = __ldg(cw4 + k * 320 + tid);
    #pragma unroll
    for (int k = 0; k < 7; k++) ev[k] = se4[k * 40 + (tid >> 3)];

    float a0 = 0.f, a1 = 0.f, a2 = 0.f, a3 = 0.f;

    #pragma unroll
    for (int k = 0; k < 7; k++) {
        const float* cf = &cv[k].x;
        #pragma unroll
        for (int j = 0; j < 4; j++) {
            unsigned cb = __float_as_uint(cf[j]);
            int sh = 31 - bb - j;
            a0 += __uint_as_float(cb ^ (~(ev[k].x << sh) & MSB));
            a1 += __uint_as_float(cb ^ (~(ev[k].y << sh) & MSB));
            a2 += __uint_as_float(cb ^ (~(ev[k].z << sh) & MSB));
            a3 += __uint_as_float(cb ^ (~(ev[k].w << sh) & MSB));
        }
    }
    if (tid < 260) {                         // tail quads 2240..2499
        float4 cv7 = __ldg(cw4 + 2240 + tid);
        uint4  ev7 = se4[280 + (tid >> 3)];
        const float* cf = &cv7.x;
        #pragma unroll
        for (int j = 0; j < 4; j++) {
            unsigned cb = __float_as_uint(cf[j]);
            int sh = 31 - bb - j;
            a0 += __uint_as_float(cb ^ (~(ev7.x << sh) & MSB));
            a1 += __uint_as_float(cb ^ (~(ev7.y << sh) & MSB));
            a2 += __uint_as_float(cb ^ (~(ev7.z << sh) & MSB));
            a3 += __uint_as_float(cb ^ (~(ev7.w << sh) & MSB));
        }
    }

    float a[4] = {a0, a1, a2, a3};
    #pragma unroll
    for (int i = 0; i < 4; i++) {
        float s = a[i];
        #pragma unroll
        for (int o = 16; o > 0; o >>= 1) s += __shfl_down_sync(0xffffffffu, s, o);
        if (lane == 0) red[wrp][i] = s;
    }
    __syncthreads();
    if (tid < 4) {
        float s = 0.0f;
        #pragma unroll
        for (int k = 0; k < 10; k++) s += red[k][tid];
        out[(b0 + tid) * C + c] = s;
    }
}

// ================= launch =======================================================================
extern "C" void kernel_launch(void* const* d_in, const int* in_sizes, int n_in,
                              void* d_out, int out_size) {
    (void)in_sizes; (void)n_in; (void)out_size;
    const float* x   = (const float*)d_in[0];
    const float* idw = (const float*)d_in[1];
    const float* lvw = (const float*)d_in[2];
    const float* cw  = (const float*)d_in[3];
    float* out = (float*)d_out;

    prep_kernel<<<PREP_BLOCKS, 256>>>(idw, lvw);
    main_kernel<<<dim3(16, 10), 320>>>(x);
    logits_kernel<<<dim3(C, B / 4), 320>>>(cw, out);
}